// round 9
// baseline (speedup 1.0000x reference)
#include <cuda_runtime.h>
#include <math.h>

#define FULL_MASK 0xFFFFFFFFu

constexpr int MAXN  = 65536;
constexpr int HID   = 32;
constexpr int MAXB  = 64;
constexpr int HCAP  = 18432;      // per HALF-graph edge capacity (avg 16384)
constexpr int CHUNK = 4096;       // edges per k_group CTA

// ---- scratch (device symbols; ONLY accessed from device code) ----
__device__ int            g_gcnt[2 * MAXB];
__device__ unsigned       g_grp[2 * MAXB * HCAP];     // packed (dl<<16 | sl)
__device__ unsigned short g_srt[2 * MAXB * HCAP];     // dst-sorted local src ids per half
__device__ int            g_start[MAXN];
__device__ int            g_deg[MAXN];
__device__ float          g_dis[MAXN];
__device__ float          g_bufA[MAXN * HID];         // g (pre-agg, UNscaled)
__device__ float          g_bufB[MAXN * HID];         // h after conv1
__device__ float          g_pooled2[2 * MAXB * HID];

// ---------------------------------------------------------------------------
__global__ void __launch_bounds__(128) k_init0() {
    g_gcnt[threadIdx.x] = 0;
}

// ---------------------------------------------------------------------------
// bin edges by (graph, dst-half): 128 bins. Atomic-free warp-match ranking,
// local counting sort in smem, bin-contiguous (coalesced) dump to g_grp.
__global__ void __launch_bounds__(512) k_group(const int* __restrict__ src,
                                               const int* __restrict__ dst,
                                               int e, int shift) {
    __shared__ unsigned short HW[16 * 128];   // per-warp hist -> warp prefix
    __shared__ int   LOFF[128];               // local bin start
    __shared__ int   BASE[128];               // global reservation
    __shared__ int   WS2[4];
    __shared__ unsigned      SEG[CHUNK];      // locally bin-sorted edges
    __shared__ unsigned char SEGB[CHUNK];     // bin of each SEG slot

    const int tid = threadIdx.x;
    const int lane = tid & 31;
    const int w = tid >> 5;                   // 0..15
    const int ml = (1 << shift) - 1;
    const int base = blockIdx.x * CHUNK;
    const int cta_cnt = min(CHUNK, e - base);

    for (int i = tid; i < 16 * 128 / 2; i += 512) ((unsigned*)HW)[i] = 0;
    __syncthreads();

    unsigned pk8[8];
    int      b8[8];
    int      rk8[8];
    #pragma unroll
    for (int j = 0; j < 8; j++) {
        int il = (w << 8) + (j << 5) + lane;   // contiguous 256 edges per warp
        bool valid = il < cta_cnt;
        unsigned amask = __ballot_sync(FULL_MASK, valid);
        b8[j] = -1;
        if (valid) {
            int i = base + il;
            int s = src[i], d = dst[i];
            int b = d >> (shift - 1);                    // (graph<<1)|half
            pk8[j] = ((unsigned)(d & ml) << 16) | (unsigned)(s & ml);
            b8[j] = b;
            unsigned peers = __match_any_sync(amask, b);
            int ldr   = __ffs(peers) - 1;
            int prior = __popc(peers & ((1u << lane) - 1));
            int oldv = 0;
            if (lane == ldr) {
                oldv = HW[(w << 7) + b];
                HW[(w << 7) + b] = (unsigned short)(oldv + __popc(peers));
            }
            oldv = __shfl_sync(amask, oldv, ldr);
            rk8[j] = oldv + prior;
        }
    }
    __syncthreads();

    // per-bin warp prefix + totals + global reservation + local scan (tid<128)
    int run = 0, vincl = 0;
    if (tid < 128) {
        #pragma unroll
        for (int ww = 0; ww < 16; ww++) {
            int c = HW[(ww << 7) + tid];
            HW[(ww << 7) + tid] = (unsigned short)run;
            run += c;
        }
        BASE[tid] = run ? atomicAdd(&g_gcnt[tid], run) : 0;
        vincl = run;
        #pragma unroll
        for (int o = 1; o < 32; o <<= 1) {
            int u = __shfl_up_sync(FULL_MASK, vincl, o);
            if (lane >= o) vincl += u;
        }
        if (lane == 31) WS2[tid >> 5] = vincl;
    }
    __syncthreads();
    if (tid < 128) {
        int wq = tid >> 5;
        int add = 0;
        #pragma unroll
        for (int q = 0; q < 3; q++) if (q < wq) add += WS2[q];
        LOFF[tid] = vincl - run + add;
    }
    __syncthreads();

    // scatter into locally sorted SEG
    #pragma unroll
    for (int j = 0; j < 8; j++) {
        int b = b8[j];
        if (b >= 0) {
            int p = LOFF[b] + (int)HW[(w << 7) + b] + rk8[j];
            SEG[p]  = pk8[j];
            SEGB[p] = (unsigned char)b;
        }
    }
    __syncthreads();

    // coalesced dump (bin runs are contiguous)
    for (int t = tid; t < cta_cnt; t += 512) {
        int b = SEGB[t];
        int idx = BASE[b] + t - LOFF[b];
        if (idx < HCAP)
            g_grp[b * HCAP + idx] = SEG[t];
    }
}

// ---------------------------------------------------------------------------
// counting sort per half-graph (512 dst bins). Atomic-free warp-match ranking.
__global__ void __launch_bounds__(512) k_sort(int shift) {
    extern __shared__ char sm[];
    unsigned short* HW     = (unsigned short*)sm;                 // [16*512] 16KB
    int*            STARTL = (int*)(sm + 16384);                  // [512]
    int*            WS     = (int*)(sm + 16384 + 2048);           // [16]
    unsigned short* RANK   = (unsigned short*)(sm + 16384 + 2048 + 64);
    unsigned short* SRT    = (unsigned short*)(sm + 16384 + 2048 + 64 + 2 * HCAP);

    const int h = blockIdx.x;
    const int tid = threadIdx.x;
    const int lane = tid & 31, w = tid >> 5;
    int cnt = g_gcnt[h];
    if (cnt > HCAP) cnt = HCAP;
    const unsigned* __restrict__ grp = &g_grp[h * HCAP];

    for (int i = tid; i < 16 * 512 / 2; i += 512) ((unsigned*)HW)[i] = 0;
    __syncthreads();

    const int chunk = (cnt + 15) >> 4;
    const int beg = w * chunk;
    const int end = min(beg + chunk, cnt);

    for (int i0 = beg; i0 < end; i0 += 32) {
        int i = i0 + lane;
        bool valid = i < end;
        unsigned amask = __ballot_sync(FULL_MASK, valid);
        if (valid) {
            unsigned pk = grp[i];
            int b = (pk >> 16) & 511;
            unsigned peers = __match_any_sync(amask, b);
            int ldr   = __ffs(peers) - 1;
            int prior = __popc(peers & ((1u << lane) - 1));
            int oldv = 0;
            if (lane == ldr) {
                oldv = HW[(w << 9) + b];
                HW[(w << 9) + b] = (unsigned short)(oldv + __popc(peers));
            }
            oldv = __shfl_sync(amask, oldv, ldr);
            RANK[i] = (unsigned short)(oldv + prior);
        }
    }
    __syncthreads();

    // per-bin warp prefix + totals
    int run = 0;
    #pragma unroll
    for (int ww = 0; ww < 16; ww++) {
        int c = HW[(ww << 9) + tid];
        HW[(ww << 9) + tid] = (unsigned short)run;
        run += c;
    }
    // block scan of totals (512 threads)
    int v = run;
    #pragma unroll
    for (int o = 1; o < 32; o <<= 1) {
        int u = __shfl_up_sync(FULL_MASK, v, o);
        if (lane >= o) v += u;
    }
    if (lane == 31) WS[w] = v;
    __syncthreads();
    if (w == 0 && lane < 16) {
        int s = WS[lane];
        #pragma unroll
        for (int o = 1; o < 16; o <<= 1) {
            int u = __shfl_up_sync(0xFFFFu, s, o);
            if (lane >= o) s += u;
        }
        WS[lane] = s;
    }
    __syncthreads();
    int excl = v - run + (w ? WS[w - 1] : 0);
    STARTL[tid] = excl;
    int node = ((h >> 1) << shift) + ((h & 1) << (shift - 1)) + tid;
    g_start[node] = excl;
    g_deg[node]   = run;
    g_dis[node]   = rsqrtf((float)(run + 1));
    __syncthreads();

    // scatter
    for (int i0 = beg; i0 < end; i0 += 32) {
        int i = i0 + lane;
        if (i < end) {
            unsigned pk = grp[i];
            int b = (pk >> 16) & 511;
            int pos = STARTL[b] + (int)HW[(w << 9) + b] + (int)RANK[i];
            SRT[pos] = (unsigned short)(pk & 0xFFFFu);
        }
    }
    __syncthreads();
    int nwords = (cnt + 1) >> 1;
    unsigned* dstw = (unsigned*)g_srt + h * (HCAP >> 1);
    const unsigned* srcw = (const unsigned*)SRT;
    for (int i = tid; i < nwords; i += 512)
        dstw[i] = srcw[i];
}

// ---------------------------------------------------------------------------
// node GEMM (NO dis scale): smem-staged X tile, broadcast LDS + FFMA.
// K=16 reads Xp (harness input); K=32 reads g_bufB. Output -> g_bufA.
template <int K>
__global__ void __launch_bounds__(512) k_gemm(const float* __restrict__ Xp,
                                              const float* __restrict__ W, int n) {
    __shared__ float Xs[256 * K];
    __shared__ float Wt[32 * 33];
    const int tid = threadIdx.x, lane = tid & 31, wid = tid >> 5;
    const float* __restrict__ X = (K == 16) ? Xp : (const float*)g_bufB;

    for (int t = tid; t < 32 * K; t += 512) {
        int o = t / K, k = t - o * K;
        Wt[k * 33 + o] = W[t];
    }
    int nbase = blockIdx.x * 256;
    int nrows = min(256, n - nbase);
    const float4* X4 = (const float4*)(X + (size_t)nbase * K);
    for (int t = tid; t < nrows * (K / 4); t += 512)
        ((float4*)Xs)[t] = X4[t];
    __syncthreads();

    float w[K];
    #pragma unroll
    for (int k = 0; k < K; k++) w[k] = Wt[k * 33 + lane];

    for (int j = 0; j < 16; j++) {
        int nd = wid * 16 + j;
        if (nd >= nrows) break;
        const float4* xr = (const float4*)(Xs + nd * K);
        float a0 = 0.f, a1 = 0.f;
        #pragma unroll
        for (int k4 = 0; k4 < K / 4; k4++) {
            float4 xv = xr[k4];
            a0 += xv.x * w[k4 * 4 + 0];
            a1 += xv.y * w[k4 * 4 + 1];
            a0 += xv.z * w[k4 * 4 + 2];
            a1 += xv.w * w[k4 * 4 + 3];
        }
        g_bufA[(size_t)(nbase + nd) * HID + lane] = a0 + a1;
    }
}

// ---------------------------------------------------------------------------
// conv1 agg: copy g_bufA*dis (full graph) to smem, aggregate own half -> g_bufB
__global__ void __launch_bounds__(1024, 1) k_conv1(const float* __restrict__ b1,
                                                   int shift) {
    extern __shared__ char sm[];
    float*  SG     = (float*)sm;                        // [1024*32]
    float*  DISF   = (float*)(sm + 131072);             // [1024] full graph
    int*    STARTs = (int*)(sm + 131072 + 4096);        // [512]
    int*    DEGs   = (int*)(sm + 131072 + 4096 + 2048); // [512]

    const int h     = blockIdx.x;
    const int half  = h & 1;
    const int gbase = (h >> 1) << shift;
    const int tid   = threadIdx.x;
    const int lane  = tid & 31;
    const int wid   = tid >> 5;
    const int c8    = lane & 7;
    const int grp4  = lane >> 3;
    const int node0 = gbase + (half << (shift - 1));

    DISF[tid] = g_dis[gbase + tid];
    if (tid < 512) {
        STARTs[tid] = g_start[node0 + tid];
        DEGs[tid]   = g_deg[node0 + tid];
    }
    __syncthreads();
    {   // copy full-graph g into smem, scaling rows by dis
        float4* SG4w = (float4*)SG;
        const float4* G4 = (const float4*)(g_bufA + (size_t)gbase * HID);
        #pragma unroll
        for (int i = 0; i < 8; i++) {
            int idx = tid + i * 1024;
            float4 vv = G4[idx];
            float d = DISF[idx >> 3];
            vv.x *= d; vv.y *= d; vv.z *= d; vv.w *= d;
            SG4w[idx] = vv;
        }
    }
    __syncthreads();

    float4 b1v = ((const float4*)b1)[c8];
    const unsigned short* __restrict__ srtb = g_srt + (size_t)h * HCAP;
    for (int it = 0; it < 16; it++) {
        int ndl = wid * 16 + it;
        int ndg = (half << (shift - 1)) + ndl;
        int st = STARTs[ndl], m = DEGs[ndl];
        const unsigned short* srtp = srtb + st;
        unsigned long long acc01 = 0ull, acc23 = 0ull;
        if (grp4 == 0) {
            ulonglong2 s0 = *(const ulonglong2*)(SG + ndg * HID + (c8 << 2));
            acc01 = s0.x; acc23 = s0.y;
        }
        int p = 0;
        while (p + 32 <= m) {
            int sv = srtp[p + lane];
            #pragma unroll
            for (int i = 0; i < 8; i++) {
                int s = __shfl_sync(FULL_MASK, sv, i * 4 + grp4);
                ulonglong2 gg = *(const ulonglong2*)(SG + s * HID + (c8 << 2));
                asm("add.rn.f32x2 %0, %0, %1;" : "+l"(acc01) : "l"(gg.x));
                asm("add.rn.f32x2 %0, %0, %1;" : "+l"(acc23) : "l"(gg.y));
            }
            p += 32;
        }
        if (p < m) {
            int r  = m - p;
            int sv = (p + lane < m) ? srtp[p + lane] : 0;
            #pragma unroll
            for (int i = 0; i < 8; i++) {
                int e2 = i * 4 + grp4;
                int s = __shfl_sync(FULL_MASK, sv, e2);
                if (e2 < r) {
                    ulonglong2 gg = *(const ulonglong2*)(SG + s * HID + (c8 << 2));
                    asm("add.rn.f32x2 %0, %0, %1;" : "+l"(acc01) : "l"(gg.x));
                    asm("add.rn.f32x2 %0, %0, %1;" : "+l"(acc23) : "l"(gg.y));
                }
            }
        }
        float ax = __uint_as_float((unsigned)acc01);
        float ay = __uint_as_float((unsigned)(acc01 >> 32));
        float az = __uint_as_float((unsigned)acc23);
        float aw = __uint_as_float((unsigned)(acc23 >> 32));
        ax += __shfl_xor_sync(FULL_MASK, ax, 8);
        ay += __shfl_xor_sync(FULL_MASK, ay, 8);
        az += __shfl_xor_sync(FULL_MASK, az, 8);
        aw += __shfl_xor_sync(FULL_MASK, aw, 8);
        ax += __shfl_xor_sync(FULL_MASK, ax, 16);
        ay += __shfl_xor_sync(FULL_MASK, ay, 16);
        az += __shfl_xor_sync(FULL_MASK, az, 16);
        aw += __shfl_xor_sync(FULL_MASK, aw, 16);
        if (grp4 == 0) {
            float d = DISF[ndg];
            float4 hh;
            hh.x = tanhf(d * ax + b1v.x);
            hh.y = tanhf(d * ay + b1v.y);
            hh.z = tanhf(d * az + b1v.z);
            hh.w = tanhf(d * aw + b1v.w);
            ((float4*)g_bufB)[(size_t)(gbase + ndg) * 8 + c8] = hh;
        }
    }
}

// ---------------------------------------------------------------------------
// conv2 agg (reads g_bufA, scales by dis at copy) + node linear + pool
__global__ void __launch_bounds__(1024, 1) k_conv2(const float* __restrict__ b2,
                                                   const float* __restrict__ Wl,
                                                   const float* __restrict__ bl,
                                                   int shift) {
    extern __shared__ char sm[];
    float*  SG     = (float*)sm;
    float*  DISF   = (float*)(sm + 131072);
    int*    STARTs = (int*)(sm + 131072 + 4096);
    int*    DEGs   = (int*)(sm + 131072 + 4096 + 2048);
    float*  Wlt    = (float*)(sm + 131072 + 4096 + 4096);       // [32*33]
    float*  POOL   = (float*)(sm + 131072 + 4096 + 4096 + 4224);// [1024]

    const int h     = blockIdx.x;
    const int half  = h & 1;
    const int gbase = (h >> 1) << shift;
    const int tid   = threadIdx.x;
    const int lane  = tid & 31;
    const int wid   = tid >> 5;
    const int c8    = lane & 7;
    const int grp4  = lane >> 3;
    const int node0 = gbase + (half << (shift - 1));

    DISF[tid] = g_dis[gbase + tid];
    if (tid < 512) {
        STARTs[tid] = g_start[node0 + tid];
        DEGs[tid]   = g_deg[node0 + tid];
    }
    {
        int r = tid >> 5, cc = tid & 31;
        Wlt[cc * 33 + r] = Wl[tid];
    }
    __syncthreads();
    {
        float4* SG4w = (float4*)SG;
        const float4* G4 = (const float4*)(g_bufA + (size_t)gbase * HID);
        #pragma unroll
        for (int i = 0; i < 8; i++) {
            int idx = tid + i * 1024;
            float4 vv = G4[idx];
            float d = DISF[idx >> 3];
            vv.x *= d; vv.y *= d; vv.z *= d; vv.w *= d;
            SG4w[idx] = vv;
        }
    }
    __syncthreads();

    float4 b2v = ((const float4*)b2)[c8];
    float wl[32];
    #pragma unroll
    for (int k = 0; k < 32; k++) wl[k] = Wlt[k * 33 + lane];
    float bll = bl[lane];
    float pacc = 0.f;
    const unsigned short* __restrict__ srtb = g_srt + (size_t)h * HCAP;
    for (int it = 0; it < 16; it++) {
        int ndl = wid * 16 + it;
        int ndg = (half << (shift - 1)) + ndl;
        int st = STARTs[ndl], m = DEGs[ndl];
        const unsigned short* srtp = srtb + st;
        unsigned long long acc01 = 0ull, acc23 = 0ull;
        if (grp4 == 0) {
            ulonglong2 s0 = *(const ulonglong2*)(SG + ndg * HID + (c8 << 2));
            acc01 = s0.x; acc23 = s0.y;
        }
        int p = 0;
        while (p + 32 <= m) {
            int sv = srtp[p + lane];
            #pragma unroll
            for (int i = 0; i < 8; i++) {
                int s = __shfl_sync(FULL_MASK, sv, i * 4 + grp4);
                ulonglong2 gg = *(const ulonglong2*)(SG + s * HID + (c8 << 2));
                asm("add.rn.f32x2 %0, %0, %1;" : "+l"(acc01) : "l"(gg.x));
                asm("add.rn.f32x2 %0, %0, %1;" : "+l"(acc23) : "l"(gg.y));
            }
            p += 32;
        }
        if (p < m) {
            int r  = m - p;
            int sv = (p + lane < m) ? srtp[p + lane] : 0;
            #pragma unroll
            for (int i = 0; i < 8; i++) {
                int e2 = i * 4 + grp4;
                int s = __shfl_sync(FULL_MASK, sv, e2);
                if (e2 < r) {
                    ulonglong2 gg = *(const ulonglong2*)(SG + s * HID + (c8 << 2));
                    asm("add.rn.f32x2 %0, %0, %1;" : "+l"(acc01) : "l"(gg.x));
                    asm("add.rn.f32x2 %0, %0, %1;" : "+l"(acc23) : "l"(gg.y));
                }
            }
        }
        float ax = __uint_as_float((unsigned)acc01);
        float ay = __uint_as_float((unsigned)(acc01 >> 32));
        float az = __uint_as_float((unsigned)acc23);
        float aw = __uint_as_float((unsigned)(acc23 >> 32));
        ax += __shfl_xor_sync(FULL_MASK, ax, 8);
        ay += __shfl_xor_sync(FULL_MASK, ay, 8);
        az += __shfl_xor_sync(FULL_MASK, az, 8);
        aw += __shfl_xor_sync(FULL_MASK, aw, 8);
        ax += __shfl_xor_sync(FULL_MASK, ax, 16);
        ay += __shfl_xor_sync(FULL_MASK, ay, 16);
        az += __shfl_xor_sync(FULL_MASK, az, 16);
        aw += __shfl_xor_sync(FULL_MASK, aw, 16);
        float h2a[4] = {0.f, 0.f, 0.f, 0.f};
        if (grp4 == 0) {
            float d = DISF[ndg];
            h2a[0] = tanhf(d * ax + b2v.x);
            h2a[1] = tanhf(d * ay + b2v.y);
            h2a[2] = tanhf(d * az + b2v.z);
            h2a[3] = tanhf(d * aw + b2v.w);
        }
        float a0 = bll, a1 = 0.f;
        #pragma unroll
        for (int cc = 0; cc < 8; cc++) {
            a0 += __shfl_sync(FULL_MASK, h2a[0], cc) * wl[cc * 4 + 0];
            a1 += __shfl_sync(FULL_MASK, h2a[1], cc) * wl[cc * 4 + 1];
            a0 += __shfl_sync(FULL_MASK, h2a[2], cc) * wl[cc * 4 + 2];
            a1 += __shfl_sync(FULL_MASK, h2a[3], cc) * wl[cc * 4 + 3];
        }
        pacc += tanhf(a0 + a1);
    }
    POOL[wid * 32 + lane] = pacc;
    __syncthreads();
    if (wid == 0) {
        float s = 0.f;
        #pragma unroll
        for (int w = 0; w < 32; w++) s += POOL[w * 32 + lane];
        g_pooled2[h * HID + lane] = s;
    }
}

// ---------------------------------------------------------------------------
__global__ void __launch_bounds__(1024) k_head(const float* __restrict__ share,
                        const float* __restrict__ Wp,  const float* __restrict__ bp,
                        const float* __restrict__ Vw1, const float* __restrict__ Vb1,
                        const float* __restrict__ Vw2, const float* __restrict__ Vb2,
                        const float* __restrict__ Vw3, const float* __restrict__ Vb3,
                        const float* __restrict__ Cw1, const float* __restrict__ Cb1,
                        const float* __restrict__ Cw2, const float* __restrict__ Cb2,
                        float* __restrict__ out, int nb) {
    __shared__ float Wpt[32 * 33], Vw1t[64 * 33], Vw2t[32 * 33],
                     Vw3t[32 * 33], Cw1t[64 * 33];
    int tid = threadIdx.x;
    int lane = tid & 31, wid = tid >> 5;
    {
        int r = tid >> 5, c = tid & 31;
        Wpt[c * 33 + r]  = Wp[tid];
        Vw2t[c * 33 + r] = Vw2[tid];
        Vw3t[c * 33 + r] = Vw3[tid];
    }
    for (int t = tid; t < 2048; t += 1024) {
        int r = t >> 6, c = t & 63;
        Vw1t[c * 33 + r] = Vw1[t];
        Cw1t[c * 33 + r] = Cw1[t];
    }
    __syncthreads();

    int b = blockIdx.x * 32 + wid;
    if (b >= nb) return;
    float pv = g_pooled2[(2 * b) * HID + lane] + g_pooled2[(2 * b + 1) * HID + lane];
    float h1 = bp[lane];
    #pragma unroll
    for (int k = 0; k < 32; k++) h1 += __shfl_sync(FULL_MASK, pv, k) * Wpt[k * 33 + lane];
    float s0 = share[b * 64 + lane];
    float s1 = share[b * 64 + 32 + lane];
    float t = Vb1[lane];
    #pragma unroll
    for (int k = 0; k < 32; k++) t += __shfl_sync(FULL_MASK, s0, k) * Vw1t[k * 33 + lane];
    #pragma unroll
    for (int k = 0; k < 32; k++) t += __shfl_sync(FULL_MASK, s1, k) * Vw1t[(k + 32) * 33 + lane];
    t = tanhf(t);
    float t2 = Vb2[lane];
    #pragma unroll
    for (int k = 0; k < 32; k++) t2 += __shfl_sync(FULL_MASK, t, k) * Vw2t[k * 33 + lane];
    t2 = tanhf(t2);
    float t3 = Vb3[lane];
    #pragma unroll
    for (int k = 0; k < 32; k++) t3 += __shfl_sync(FULL_MASK, t2, k) * Vw3t[k * 33 + lane];
    float z = Cb1[lane];
    #pragma unroll
    for (int k = 0; k < 32; k++) z += __shfl_sync(FULL_MASK, h1, k) * Cw1t[k * 33 + lane];
    #pragma unroll
    for (int k = 0; k < 32; k++) z += __shfl_sync(FULL_MASK, t3, k) * Cw1t[(k + 32) * 33 + lane];
    z = tanhf(z);
    float p = z * Cw2[lane];
    #pragma unroll
    for (int o = 16; o > 0; o >>= 1) p += __shfl_down_sync(FULL_MASK, p, o);
    if (lane == 0) out[b] = p + Cb2[0];
}

// ---------------------------------------------------------------------------
extern "C" void kernel_launch(void* const* d_in, const int* in_sizes, int n_in,
                              void* d_out, int out_size) {
    const float* x      = (const float*)d_in[0];
    const int*   edge   = (const int*)  d_in[1];
    const float* share  = (const float*)d_in[3];
    const float* W1 = (const float*)d_in[4];   const float* b1 = (const float*)d_in[5];
    const float* W2 = (const float*)d_in[6];   const float* b2 = (const float*)d_in[7];
    const float* Wl = (const float*)d_in[8];   const float* bl = (const float*)d_in[9];
    const float* Wp = (const float*)d_in[10];  const float* bp = (const float*)d_in[11];
    const float* Vw1 = (const float*)d_in[12]; const float* Vb1 = (const float*)d_in[13];
    const float* Vw2 = (const float*)d_in[14]; const float* Vb2 = (const float*)d_in[15];
    const float* Vw3 = (const float*)d_in[16]; const float* Vb3 = (const float*)d_in[17];
    const float* Cw1 = (const float*)d_in[18]; const float* Cb1 = (const float*)d_in[19];
    const float* Cw2 = (const float*)d_in[20]; const float* Cb2 = (const float*)d_in[21];

    const int n  = in_sizes[0] / 16;
    const int e  = in_sizes[1] / 2;
    const int nb = in_sizes[3] / 64;
    const int* src = edge;
    const int* dst = edge + e;
    float* out = (float*)d_out;

    int pp = n / nb;                     // 1024
    int shift = 0;
    while ((1 << shift) < pp) shift++;
    const int nh = nb * 2;

    const int SM_SORT  = 16384 + 2048 + 64 + 2 * HCAP + 2 * HCAP;
    const int SM_CONV1 = 131072 + 4096 + 2048 + 2048;
    const int SM_CONV2 = 131072 + 4096 + 4096 + 4224 + 4096;
    static int smem_set = 0;
    if (!smem_set) {
        cudaFuncSetAttribute(k_sort,  cudaFuncAttributeMaxDynamicSharedMemorySize, SM_SORT);
        cudaFuncSetAttribute(k_conv1, cudaFuncAttributeMaxDynamicSharedMemorySize, SM_CONV1);
        cudaFuncSetAttribute(k_conv2, cudaFuncAttributeMaxDynamicSharedMemorySize, SM_CONV2);
        smem_set = 1;
    }

    k_init0<<<1, 128>>>();
    k_group<<<(e + CHUNK - 1) / CHUNK, 512>>>(src, dst, e, shift);
    k_sort<<<nh, 512, SM_SORT>>>(shift);
    k_gemm<16><<<(n + 255) / 256, 512>>>(x, W1, n);          // x -> g_bufA
    k_conv1<<<nh, 1024, SM_CONV1>>>(b1, shift);              // g_bufA -> g_bufB
    k_gemm<32><<<(n + 255) / 256, 512>>>(x, W2, n);          // g_bufB -> g_bufA
    k_conv2<<<nh, 1024, SM_CONV2>>>(b2, Wl, bl, shift);      // g_bufA -> g_pooled2
    k_head<<<(nb + 31) / 32, 1024>>>(share, Wp, bp, Vw1, Vb1, Vw2, Vb2, Vw3, Vb3,
                                     Cw1, Cb1, Cw2, Cb2, out, nb);
}

// round 10
// speedup vs baseline: 1.1446x; 1.1446x over previous
#include <cuda_runtime.h>
#include <math.h>

#define FULL_MASK 0xFFFFFFFFu

constexpr int MAXN  = 65536;
constexpr int HID   = 32;
constexpr int MAXB  = 64;
constexpr int HCAP  = 18432;      // per HALF-graph edge capacity (avg 16384)
constexpr int CHUNK = 4096;       // edges per k_group CTA

// ---- scratch (device symbols; ONLY accessed from device code) ----
__device__ int            g_gcnt[2 * MAXB];
__device__ unsigned       g_grp[2 * MAXB * HCAP];     // packed (dl<<16 | sl)
__device__ unsigned short g_srt[2 * MAXB * HCAP];     // dst-sorted local src ids per half
__device__ int            g_start[MAXN];
__device__ int            g_deg[MAXN];
__device__ float          g_dis[MAXN];
__device__ float          g_bufA[MAXN * HID];         // g1 (unscaled)
__device__ float          g_bufB[MAXN * HID];         // g2 (unscaled)
__device__ float          g_pooled2[2 * MAXB * HID];

// ---------------------------------------------------------------------------
__global__ void __launch_bounds__(128) k_init0() {
    g_gcnt[threadIdx.x] = 0;
}

// ---------------------------------------------------------------------------
// bin edges by (graph, dst-half): 128 bins, smem rank atomics (R8 version)
__global__ void __launch_bounds__(512) k_group(const int* __restrict__ src,
                                               const int* __restrict__ dst,
                                               int e, int shift) {
    __shared__ int sh_cnt[128];
    __shared__ int sh_base[128];
    int tid = threadIdx.x;
    if (tid < 128) sh_cnt[tid] = 0;
    __syncthreads();

    const int ml = (1 << shift) - 1;
    int base = blockIdx.x * CHUNK;
    int      mybin[8];
    int      myrank[8];
    unsigned mypk[8];

    int t8 = base + tid * 8;
    if (t8 + 7 < e) {
        const int4* s4 = (const int4*)(src + t8);
        const int4* d4 = (const int4*)(dst + t8);
        int4 sa = s4[0], sb = s4[1];
        int4 da = d4[0], db = d4[1];
        int ss[8] = {sa.x, sa.y, sa.z, sa.w, sb.x, sb.y, sb.z, sb.w};
        int dd[8] = {da.x, da.y, da.z, da.w, db.x, db.y, db.z, db.w};
        #pragma unroll
        for (int j = 0; j < 8; j++) {
            int b = dd[j] >> (shift - 1);
            mybin[j]  = b;
            mypk[j]   = ((unsigned)(dd[j] & ml) << 16) | (unsigned)(ss[j] & ml);
            myrank[j] = atomicAdd(&sh_cnt[b], 1);
        }
    } else {
        #pragma unroll
        for (int j = 0; j < 8; j++) {
            int i = t8 + j;
            if (i < e) {
                int s = src[i], d = dst[i];
                int b = d >> (shift - 1);
                mybin[j]  = b;
                mypk[j]   = ((unsigned)(d & ml) << 16) | (unsigned)(s & ml);
                myrank[j] = atomicAdd(&sh_cnt[b], 1);
            } else mybin[j] = -1;
        }
    }
    __syncthreads();
    if (tid < 128) {
        int c = sh_cnt[tid];
        sh_base[tid] = c ? atomicAdd(&g_gcnt[tid], c) : 0;
    }
    __syncthreads();
    #pragma unroll
    for (int j = 0; j < 8; j++) {
        int b = mybin[j];
        if (b >= 0) {
            int idx = sh_base[b] + myrank[j];
            if (idx < HCAP)
                g_grp[b * HCAP + idx] = mypk[j];
        }
    }
}

// ---------------------------------------------------------------------------
// counting sort per half-graph (R8 atomic version) + fused GEMM1 tail:
// g_bufA[node] = x[node] @ W1^T (unscaled) for this CTA's 512 nodes.
__global__ void __launch_bounds__(512) k_sort(const float* __restrict__ x,
                                              const float* __restrict__ W1,
                                              int shift) {
    extern __shared__ char sm[];
    int*            HIST = (int*)sm;                              // [512]
    int*            WS   = (int*)(sm + 2048);                     // [16]
    unsigned short* RANK = (unsigned short*)(sm + 2048 + 64);     // [HCAP]
    unsigned short* SRT  = (unsigned short*)(sm + 2048 + 64 + 2 * HCAP);
    float*          Wt   = (float*)(sm + 2048 + 64 + 4 * HCAP);   // [16*33]

    const int h   = blockIdx.x;
    const int tid = threadIdx.x;
    const int lane = tid & 31, wid = tid >> 5;
    int cnt = g_gcnt[h];
    if (cnt > HCAP) cnt = HCAP;
    const unsigned* __restrict__ grp = &g_grp[h * HCAP];
    const int node0 = ((h >> 1) << shift) + ((h & 1) << (shift - 1));

    HIST[tid] = 0;
    {   // stage W1 transposed [16][33]
        int o = tid >> 4, k = tid & 15;
        Wt[k * 33 + o] = W1[tid];
    }
    __syncthreads();
    for (int i = tid; i < cnt; i += 512) {
        unsigned pk = grp[i];
        RANK[i] = (unsigned short)atomicAdd(&HIST[(pk >> 16) & 511], 1);
    }
    __syncthreads();
    int c = HIST[tid];
    int v = c;
    #pragma unroll
    for (int o = 1; o < 32; o <<= 1) {
        int u = __shfl_up_sync(FULL_MASK, v, o);
        if (lane >= o) v += u;
    }
    if (lane == 31) WS[wid] = v;
    __syncthreads();
    if (wid == 0 && lane < 16) {
        int s = WS[lane];
        #pragma unroll
        for (int o = 1; o < 16; o <<= 1) {
            int u = __shfl_up_sync(0xFFFFu, s, o);
            if (lane >= o) s += u;
        }
        WS[lane] = s;
    }
    __syncthreads();
    int excl = v - c + (wid ? WS[wid - 1] : 0);
    HIST[tid] = excl;
    g_start[node0 + tid] = excl;
    g_deg[node0 + tid]   = c;
    g_dis[node0 + tid]   = rsqrtf((float)(c + 1));
    __syncthreads();
    for (int i = tid; i < cnt; i += 512) {
        unsigned pk = grp[i];
        int pos = HIST[(pk >> 16) & 511] + (int)RANK[i];
        SRT[pos] = (unsigned short)(pk & 0xFFFFu);
    }
    __syncthreads();
    int nwords = (cnt + 1) >> 1;
    unsigned* dstw = (unsigned*)g_srt + h * (HCAP >> 1);
    const unsigned* srcw = (const unsigned*)SRT;
    for (int i = tid; i < nwords; i += 512)
        dstw[i] = srcw[i];

    // ---- fused GEMM1: g_bufA[node] = x @ W1^T for this CTA's 512 nodes ----
    float w[16];
    #pragma unroll
    for (int k = 0; k < 16; k++) w[k] = Wt[k * 33 + lane];
    #pragma unroll 2
    for (int it = 0; it < 32; it++) {
        int node = node0 + wid * 32 + it;
        float xv = (lane < 16) ? x[(size_t)node * 16 + lane] : 0.f;
        float a0 = 0.f, a1 = 0.f;
        #pragma unroll
        for (int k = 0; k < 16; k += 2) {
            a0 += __shfl_sync(FULL_MASK, xv, k)     * w[k];
            a1 += __shfl_sync(FULL_MASK, xv, k + 1) * w[k + 1];
        }
        g_bufA[(size_t)node * HID + lane] = a0 + a1;
    }
}

// ---------------------------------------------------------------------------
// conv1: copy g_bufA*dis (full graph) to smem, aggregate own half, tanh,
// then fused GEMM2: g_bufB[node] = h @ W2^T (unscaled).
__global__ void __launch_bounds__(1024, 1) k_conv1(const float* __restrict__ b1,
                                                   const float* __restrict__ W2,
                                                   int shift) {
    extern __shared__ char sm[];
    float*  SG     = (float*)sm;                        // [1024*32]
    float*  DISF   = (float*)(sm + 131072);             // [1024]
    int*    STARTs = (int*)(sm + 131072 + 4096);        // [512]
    int*    DEGs   = (int*)(sm + 131072 + 4096 + 2048); // [512]
    float*  W2t    = (float*)(sm + 131072 + 4096 + 4096);   // [32*33]

    const int h     = blockIdx.x;
    const int half  = h & 1;
    const int gbase = (h >> 1) << shift;
    const int tid   = threadIdx.x;
    const int lane  = tid & 31;
    const int wid   = tid >> 5;
    const int c8    = lane & 7;
    const int grp4  = lane >> 3;
    const int node0 = gbase + (half << (shift - 1));

    DISF[tid] = g_dis[gbase + tid];
    if (tid < 512) {
        STARTs[tid] = g_start[node0 + tid];
        DEGs[tid]   = g_deg[node0 + tid];
    }
    {
        int r = tid >> 5, cc = tid & 31;
        W2t[cc * 33 + r] = W2[tid];
    }
    __syncthreads();
    {   // copy full-graph g1 into smem, scaling rows by dis
        float4* SG4w = (float4*)SG;
        const float4* G4 = (const float4*)(g_bufA + (size_t)gbase * HID);
        #pragma unroll
        for (int i = 0; i < 8; i++) {
            int idx = tid + i * 1024;
            float4 vv = G4[idx];
            float d = DISF[idx >> 3];
            vv.x *= d; vv.y *= d; vv.z *= d; vv.w *= d;
            SG4w[idx] = vv;
        }
    }
    __syncthreads();

    float4 b1v = ((const float4*)b1)[c8];
    float w2[32];
    #pragma unroll
    for (int k = 0; k < 32; k++) w2[k] = W2t[k * 33 + lane];
    const unsigned short* __restrict__ srtb = g_srt + (size_t)h * HCAP;
    for (int it = 0; it < 16; it++) {
        int ndl = wid * 16 + it;
        int ndg = (half << (shift - 1)) + ndl;
        int st = STARTs[ndl], m = DEGs[ndl];
        const unsigned short* srtp = srtb + st;
        unsigned long long acc01 = 0ull, acc23 = 0ull;
        if (grp4 == 0) {
            ulonglong2 s0 = *(const ulonglong2*)(SG + ndg * HID + (c8 << 2));
            acc01 = s0.x; acc23 = s0.y;
        }
        int p = 0;
        while (p + 32 <= m) {
            int sv = srtp[p + lane];
            #pragma unroll
            for (int i = 0; i < 8; i++) {
                int s = __shfl_sync(FULL_MASK, sv, i * 4 + grp4);
                ulonglong2 gg = *(const ulonglong2*)(SG + s * HID + (c8 << 2));
                asm("add.rn.f32x2 %0, %0, %1;" : "+l"(acc01) : "l"(gg.x));
                asm("add.rn.f32x2 %0, %0, %1;" : "+l"(acc23) : "l"(gg.y));
            }
            p += 32;
        }
        if (p < m) {
            int r  = m - p;
            int sv = (p + lane < m) ? srtp[p + lane] : 0;
            #pragma unroll
            for (int i = 0; i < 8; i++) {
                int e2 = i * 4 + grp4;
                int s = __shfl_sync(FULL_MASK, sv, e2);
                if (e2 < r) {
                    ulonglong2 gg = *(const ulonglong2*)(SG + s * HID + (c8 << 2));
                    asm("add.rn.f32x2 %0, %0, %1;" : "+l"(acc01) : "l"(gg.x));
                    asm("add.rn.f32x2 %0, %0, %1;" : "+l"(acc23) : "l"(gg.y));
                }
            }
        }
        float ax = __uint_as_float((unsigned)acc01);
        float ay = __uint_as_float((unsigned)(acc01 >> 32));
        float az = __uint_as_float((unsigned)acc23);
        float aw = __uint_as_float((unsigned)(acc23 >> 32));
        ax += __shfl_xor_sync(FULL_MASK, ax, 8);
        ay += __shfl_xor_sync(FULL_MASK, ay, 8);
        az += __shfl_xor_sync(FULL_MASK, az, 8);
        aw += __shfl_xor_sync(FULL_MASK, aw, 8);
        ax += __shfl_xor_sync(FULL_MASK, ax, 16);
        ay += __shfl_xor_sync(FULL_MASK, ay, 16);
        az += __shfl_xor_sync(FULL_MASK, az, 16);
        aw += __shfl_xor_sync(FULL_MASK, aw, 16);
        float h2a[4] = {0.f, 0.f, 0.f, 0.f};
        if (grp4 == 0) {
            float d = DISF[ndg];
            h2a[0] = tanhf(d * ax + b1v.x);
            h2a[1] = tanhf(d * ay + b1v.y);
            h2a[2] = tanhf(d * az + b1v.z);
            h2a[3] = tanhf(d * aw + b1v.w);
        }
        // fused GEMM2: g2[lane] = sum_k h[k] * W2[lane][k]
        float a0 = 0.f, a1 = 0.f;
        #pragma unroll
        for (int cc = 0; cc < 8; cc++) {
            a0 += __shfl_sync(FULL_MASK, h2a[0], cc) * w2[cc * 4 + 0];
            a1 += __shfl_sync(FULL_MASK, h2a[1], cc) * w2[cc * 4 + 1];
            a0 += __shfl_sync(FULL_MASK, h2a[2], cc) * w2[cc * 4 + 2];
            a1 += __shfl_sync(FULL_MASK, h2a[3], cc) * w2[cc * 4 + 3];
        }
        g_bufB[(size_t)(gbase + ndg) * HID + lane] = a0 + a1;
    }
}

// ---------------------------------------------------------------------------
// conv2: copy g_bufB*dis to smem, aggregate own half + node linear + pool
__global__ void __launch_bounds__(1024, 1) k_conv2(const float* __restrict__ b2,
                                                   const float* __restrict__ Wl,
                                                   const float* __restrict__ bl,
                                                   int shift) {
    extern __shared__ char sm[];
    float*  SG     = (float*)sm;
    float*  DISF   = (float*)(sm + 131072);
    int*    STARTs = (int*)(sm + 131072 + 4096);
    int*    DEGs   = (int*)(sm + 131072 + 4096 + 2048);
    float*  Wlt    = (float*)(sm + 131072 + 4096 + 4096);       // [32*33]
    float*  POOL   = (float*)(sm + 131072 + 4096 + 4096 + 4224);// [1024]

    const int h     = blockIdx.x;
    const int half  = h & 1;
    const int gbase = (h >> 1) << shift;
    const int tid   = threadIdx.x;
    const int lane  = tid & 31;
    const int wid   = tid >> 5;
    const int c8    = lane & 7;
    const int grp4  = lane >> 3;
    const int node0 = gbase + (half << (shift - 1));

    DISF[tid] = g_dis[gbase + tid];
    if (tid < 512) {
        STARTs[tid] = g_start[node0 + tid];
        DEGs[tid]   = g_deg[node0 + tid];
    }
    {
        int r = tid >> 5, cc = tid & 31;
        Wlt[cc * 33 + r] = Wl[tid];
    }
    __syncthreads();
    {
        float4* SG4w = (float4*)SG;
        const float4* G4 = (const float4*)(g_bufB + (size_t)gbase * HID);
        #pragma unroll
        for (int i = 0; i < 8; i++) {
            int idx = tid + i * 1024;
            float4 vv = G4[idx];
            float d = DISF[idx >> 3];
            vv.x *= d; vv.y *= d; vv.z *= d; vv.w *= d;
            SG4w[idx] = vv;
        }
    }
    __syncthreads();

    float4 b2v = ((const float4*)b2)[c8];
    float wl[32];
    #pragma unroll
    for (int k = 0; k < 32; k++) wl[k] = Wlt[k * 33 + lane];
    float bll = bl[lane];
    float pacc = 0.f;
    const unsigned short* __restrict__ srtb = g_srt + (size_t)h * HCAP;
    for (int it = 0; it < 16; it++) {
        int ndl = wid * 16 + it;
        int ndg = (half << (shift - 1)) + ndl;
        int st = STARTs[ndl], m = DEGs[ndl];
        const unsigned short* srtp = srtb + st;
        unsigned long long acc01 = 0ull, acc23 = 0ull;
        if (grp4 == 0) {
            ulonglong2 s0 = *(const ulonglong2*)(SG + ndg * HID + (c8 << 2));
            acc01 = s0.x; acc23 = s0.y;
        }
        int p = 0;
        while (p + 32 <= m) {
            int sv = srtp[p + lane];
            #pragma unroll
            for (int i = 0; i < 8; i++) {
                int s = __shfl_sync(FULL_MASK, sv, i * 4 + grp4);
                ulonglong2 gg = *(const ulonglong2*)(SG + s * HID + (c8 << 2));
                asm("add.rn.f32x2 %0, %0, %1;" : "+l"(acc01) : "l"(gg.x));
                asm("add.rn.f32x2 %0, %0, %1;" : "+l"(acc23) : "l"(gg.y));
            }
            p += 32;
        }
        if (p < m) {
            int r  = m - p;
            int sv = (p + lane < m) ? srtp[p + lane] : 0;
            #pragma unroll
            for (int i = 0; i < 8; i++) {
                int e2 = i * 4 + grp4;
                int s = __shfl_sync(FULL_MASK, sv, e2);
                if (e2 < r) {
                    ulonglong2 gg = *(const ulonglong2*)(SG + s * HID + (c8 << 2));
                    asm("add.rn.f32x2 %0, %0, %1;" : "+l"(acc01) : "l"(gg.x));
                    asm("add.rn.f32x2 %0, %0, %1;" : "+l"(acc23) : "l"(gg.y));
                }
            }
        }
        float ax = __uint_as_float((unsigned)acc01);
        float ay = __uint_as_float((unsigned)(acc01 >> 32));
        float az = __uint_as_float((unsigned)acc23);
        float aw = __uint_as_float((unsigned)(acc23 >> 32));
        ax += __shfl_xor_sync(FULL_MASK, ax, 8);
        ay += __shfl_xor_sync(FULL_MASK, ay, 8);
        az += __shfl_xor_sync(FULL_MASK, az, 8);
        aw += __shfl_xor_sync(FULL_MASK, aw, 8);
        ax += __shfl_xor_sync(FULL_MASK, ax, 16);
        ay += __shfl_xor_sync(FULL_MASK, ay, 16);
        az += __shfl_xor_sync(FULL_MASK, az, 16);
        aw += __shfl_xor_sync(FULL_MASK, aw, 16);
        float h2a[4] = {0.f, 0.f, 0.f, 0.f};
        if (grp4 == 0) {
            float d = DISF[ndg];
            h2a[0] = tanhf(d * ax + b2v.x);
            h2a[1] = tanhf(d * ay + b2v.y);
            h2a[2] = tanhf(d * az + b2v.z);
            h2a[3] = tanhf(d * aw + b2v.w);
        }
        float a0 = bll, a1 = 0.f;
        #pragma unroll
        for (int cc = 0; cc < 8; cc++) {
            a0 += __shfl_sync(FULL_MASK, h2a[0], cc) * wl[cc * 4 + 0];
            a1 += __shfl_sync(FULL_MASK, h2a[1], cc) * wl[cc * 4 + 1];
            a0 += __shfl_sync(FULL_MASK, h2a[2], cc) * wl[cc * 4 + 2];
            a1 += __shfl_sync(FULL_MASK, h2a[3], cc) * wl[cc * 4 + 3];
        }
        pacc += tanhf(a0 + a1);
    }
    POOL[wid * 32 + lane] = pacc;
    __syncthreads();
    if (wid == 0) {
        float s = 0.f;
        #pragma unroll
        for (int w = 0; w < 32; w++) s += POOL[w * 32 + lane];
        g_pooled2[h * HID + lane] = s;
    }
}

// ---------------------------------------------------------------------------
__global__ void __launch_bounds__(1024) k_head(const float* __restrict__ share,
                        const float* __restrict__ Wp,  const float* __restrict__ bp,
                        const float* __restrict__ Vw1, const float* __restrict__ Vb1,
                        const float* __restrict__ Vw2, const float* __restrict__ Vb2,
                        const float* __restrict__ Vw3, const float* __restrict__ Vb3,
                        const float* __restrict__ Cw1, const float* __restrict__ Cb1,
                        const float* __restrict__ Cw2, const float* __restrict__ Cb2,
                        float* __restrict__ out, int nb) {
    __shared__ float Wpt[32 * 33], Vw1t[64 * 33], Vw2t[32 * 33],
                     Vw3t[32 * 33], Cw1t[64 * 33];
    int tid = threadIdx.x;
    int lane = tid & 31, wid = tid >> 5;
    {
        int r = tid >> 5, c = tid & 31;
        Wpt[c * 33 + r]  = Wp[tid];
        Vw2t[c * 33 + r] = Vw2[tid];
        Vw3t[c * 33 + r] = Vw3[tid];
    }
    for (int t = tid; t < 2048; t += 1024) {
        int r = t >> 6, c = t & 63;
        Vw1t[c * 33 + r] = Vw1[t];
        Cw1t[c * 33 + r] = Cw1[t];
    }
    __syncthreads();

    int b = blockIdx.x * 32 + wid;
    if (b >= nb) return;
    float pv = g_pooled2[(2 * b) * HID + lane] + g_pooled2[(2 * b + 1) * HID + lane];
    float h1 = bp[lane];
    #pragma unroll
    for (int k = 0; k < 32; k++) h1 += __shfl_sync(FULL_MASK, pv, k) * Wpt[k * 33 + lane];
    float s0 = share[b * 64 + lane];
    float s1 = share[b * 64 + 32 + lane];
    float t = Vb1[lane];
    #pragma unroll
    for (int k = 0; k < 32; k++) t += __shfl_sync(FULL_MASK, s0, k) * Vw1t[k * 33 + lane];
    #pragma unroll
    for (int k = 0; k < 32; k++) t += __shfl_sync(FULL_MASK, s1, k) * Vw1t[(k + 32) * 33 + lane];
    t = tanhf(t);
    float t2 = Vb2[lane];
    #pragma unroll
    for (int k = 0; k < 32; k++) t2 += __shfl_sync(FULL_MASK, t, k) * Vw2t[k * 33 + lane];
    t2 = tanhf(t2);
    float t3 = Vb3[lane];
    #pragma unroll
    for (int k = 0; k < 32; k++) t3 += __shfl_sync(FULL_MASK, t2, k) * Vw3t[k * 33 + lane];
    float z = Cb1[lane];
    #pragma unroll
    for (int k = 0; k < 32; k++) z += __shfl_sync(FULL_MASK, h1, k) * Cw1t[k * 33 + lane];
    #pragma unroll
    for (int k = 0; k < 32; k++) z += __shfl_sync(FULL_MASK, t3, k) * Cw1t[(k + 32) * 33 + lane];
    z = tanhf(z);
    float p = z * Cw2[lane];
    #pragma unroll
    for (int o = 16; o > 0; o >>= 1) p += __shfl_down_sync(FULL_MASK, p, o);
    if (lane == 0) out[b] = p + Cb2[0];
}

// ---------------------------------------------------------------------------
extern "C" void kernel_launch(void* const* d_in, const int* in_sizes, int n_in,
                              void* d_out, int out_size) {
    const float* x      = (const float*)d_in[0];
    const int*   edge   = (const int*)  d_in[1];
    const float* share  = (const float*)d_in[3];
    const float* W1 = (const float*)d_in[4];   const float* b1 = (const float*)d_in[5];
    const float* W2 = (const float*)d_in[6];   const float* b2 = (const float*)d_in[7];
    const float* Wl = (const float*)d_in[8];   const float* bl = (const float*)d_in[9];
    const float* Wp = (const float*)d_in[10];  const float* bp = (const float*)d_in[11];
    const float* Vw1 = (const float*)d_in[12]; const float* Vb1 = (const float*)d_in[13];
    const float* Vw2 = (const float*)d_in[14]; const float* Vb2 = (const float*)d_in[15];
    const float* Vw3 = (const float*)d_in[16]; const float* Vb3 = (const float*)d_in[17];
    const float* Cw1 = (const float*)d_in[18]; const float* Cb1 = (const float*)d_in[19];
    const float* Cw2 = (const float*)d_in[20]; const float* Cb2 = (const float*)d_in[21];

    const int n  = in_sizes[0] / 16;
    const int e  = in_sizes[1] / 2;
    const int nb = in_sizes[3] / 64;
    const int* src = edge;
    const int* dst = edge + e;
    float* out = (float*)d_out;

    int pp = n / nb;                     // 1024
    int shift = 0;
    while ((1 << shift) < pp) shift++;
    const int nh = nb * 2;

    const int SM_SORT  = 2048 + 64 + 4 * HCAP + 16 * 33 * 4;
    const int SM_CONV1 = 131072 + 4096 + 2048 + 2048 + 32 * 33 * 4;
    const int SM_CONV2 = 131072 + 4096 + 2048 + 2048 + 32 * 33 * 4 + 4096;
    static int smem_set = 0;
    if (!smem_set) {
        cudaFuncSetAttribute(k_sort,  cudaFuncAttributeMaxDynamicSharedMemorySize, SM_SORT);
        cudaFuncSetAttribute(k_conv1, cudaFuncAttributeMaxDynamicSharedMemorySize, SM_CONV1);
        cudaFuncSetAttribute(k_conv2, cudaFuncAttributeMaxDynamicSharedMemorySize, SM_CONV2);
        smem_set = 1;
    }

    k_init0<<<1, 128>>>();
    k_group<<<(e + CHUNK - 1) / CHUNK, 512>>>(src, dst, e, shift);
    k_sort<<<nh, 512, SM_SORT>>>(x, W1, shift);              // + fused GEMM1 -> g_bufA
    k_conv1<<<nh, 1024, SM_CONV1>>>(b1, W2, shift);          // agg1 + fused GEMM2 -> g_bufB
    k_conv2<<<nh, 1024, SM_CONV2>>>(b2, Wl, bl, shift);      // agg2 + Wl + pool
    k_head<<<(nb + 31) / 32, 1024>>>(share, Wp, bp, Vw1, Vb1, Vw2, Vb2, Vw3, Vb3,
                                     Cw1, Cb1, Cw2, Cb2, out, nb);
}